// round 4
// baseline (speedup 1.0000x reference)
#include <cuda_runtime.h>
#include <math_constants.h>
#include <cstdint>

#define BSZ   2
#define SEQ   2048
#define HID   1024
#define NH    16
#define HD    64

// Scratch for projected Q/K/V, laid out [b*NH+h][s][d]
__device__ float g_q[BSZ * NH * SEQ * HD];
__device__ float g_k[BSZ * NH * SEQ * HD];
__device__ float g_v[BSZ * NH * SEQ * HD];

// ============================================================================
// helpers
// ============================================================================
__device__ __forceinline__ uint32_t smem_u32(const void* p) {
    uint32_t a;
    asm("{ .reg .u64 t; cvta.to.shared.u64 t, %1; cvt.u32.u64 %0, t; }"
        : "=r"(a) : "l"(p));
    return a;
}
__device__ __forceinline__ void cp16(uint32_t s, const void* g) {
    asm volatile("cp.async.cg.shared.global [%0], [%1], 16;" :: "r"(s), "l"(g));
}
__device__ __forceinline__ void cp_commit() {
    asm volatile("cp.async.commit_group;" ::: "memory");
}
__device__ __forceinline__ void cp_wait2() {
    asm volatile("cp.async.wait_group 2;" ::: "memory");
}
__device__ __forceinline__ uint32_t f2tf(float f) {
    uint32_t r;
    asm("cvt.rna.tf32.f32 %0, %1;" : "=r"(r) : "f"(f));
    return r;
}
__device__ __forceinline__ void ldm4(uint32_t* r, uint32_t addr) {
    asm volatile("ldmatrix.sync.aligned.m8n8.x4.shared.b16 {%0,%1,%2,%3}, [%4];"
                 : "=r"(r[0]), "=r"(r[1]), "=r"(r[2]), "=r"(r[3]) : "r"(addr));
}
__device__ __forceinline__ void mma_tf32(float* c, const uint32_t* a,
                                         uint32_t b0, uint32_t b1) {
    asm volatile(
        "mma.sync.aligned.m16n8k8.row.col.f32.tf32.tf32.f32 "
        "{%0,%1,%2,%3}, {%4,%5,%6,%7}, {%8,%9}, {%0,%1,%2,%3};"
        : "+f"(c[0]), "+f"(c[1]), "+f"(c[2]), "+f"(c[3])
        : "r"(a[0]), "r"(a[1]), "r"(a[2]), "r"(a[3]), "r"(b0), "r"(b1));
}

// ============================================================================
// QKV projection (unchanged from R3): out[m][n] = sum_k X[m][k]*W[n][k] + b[n]
// ============================================================================
#define QPITCH   36
#define QA_BYTES (128 * QPITCH * 4)
#define QSTAGE   (2 * QA_BYTES)
#define QSTAGES  3
#define QKV_SMEM (QSTAGES * QSTAGE)
#define QNKT     (HID / 32)

__global__ __launch_bounds__(256) void qkv_mma_kernel(
    const float* __restrict__ X,
    const float* __restrict__ Wq, const float* __restrict__ bq,
    const float* __restrict__ Wk, const float* __restrict__ bk,
    const float* __restrict__ Wv, const float* __restrict__ bv)
{
    const float* W; const float* bias; float* out;
    if (blockIdx.z == 0)      { W = Wq; bias = bq; out = g_q; }
    else if (blockIdx.z == 1) { W = Wk; bias = bk; out = g_k; }
    else                      { W = Wv; bias = bv; out = g_v; }

    extern __shared__ char smem[];
    const uint32_t sb = smem_u32(smem);

    const int tid  = threadIdx.x;
    const int wid  = tid >> 5;
    const int lane = tid & 31;
    const int wm   = wid >> 1;
    const int wn   = wid & 1;
    const int m0   = blockIdx.x * 128;
    const int n0   = blockIdx.y * 128;

    const float* gA0 = X + (size_t)m0 * HID;
    const float* gB0 = W + (size_t)n0 * HID;

    auto load_stage = [&](int stage, int kt) {
        const uint32_t sA = sb + stage * QSTAGE;
        const uint32_t sB = sA + QA_BYTES;
        const float* gA = gA0 + kt * 32;
        const float* gB = gB0 + kt * 32;
        #pragma unroll
        for (int i = 0; i < 4; i++) {
            int cid = tid + (i << 8);
            int row = cid >> 3;
            int c   = cid & 7;
            uint32_t off = row * (QPITCH * 4) + c * 16;
            cp16(sA + off, gA + row * HID + c * 4);
            cp16(sB + off, gB + row * HID + c * 4);
        }
    };

    load_stage(0, 0); cp_commit();
    load_stage(1, 1); cp_commit();
    load_stage(2, 2); cp_commit();

    float acc[2][8][4];
    #pragma unroll
    for (int mt = 0; mt < 2; mt++)
        #pragma unroll
        for (int nt = 0; nt < 8; nt++)
            acc[mt][nt][0] = acc[mt][nt][1] = acc[mt][nt][2] = acc[mt][nt][3] = 0.f;

    const int a_row = (lane & 15);
    const int a_kof = (lane >> 4) * 4;
    const int b_row = (lane & 7) + ((lane >> 4) << 3);
    const int b_kof = ((lane >> 3) & 1) * 4;

    for (int kt = 0; kt < QNKT; kt++) {
        cp_wait2();
        __syncthreads();
        const uint32_t sA = sb + (kt % QSTAGES) * QSTAGE;
        const uint32_t sB = sA + QA_BYTES;

        #pragma unroll
        for (int k8 = 0; k8 < 4; k8++) {
            const int kc = k8 * 8;
            uint32_t af[2][4], bf[4][4];
            #pragma unroll
            for (int mt = 0; mt < 2; mt++)
                ldm4(af[mt], sA + ((wm * 32 + mt * 16 + a_row) * QPITCH + kc + a_kof) * 4);
            #pragma unroll
            for (int np = 0; np < 4; np++)
                ldm4(bf[np], sB + ((wn * 64 + np * 16 + b_row) * QPITCH + kc + b_kof) * 4);
            #pragma unroll
            for (int mt = 0; mt < 2; mt++)
                #pragma unroll
                for (int i = 0; i < 4; i++)
                    af[mt][i] = f2tf(__uint_as_float(af[mt][i]));
            #pragma unroll
            for (int np = 0; np < 4; np++)
                #pragma unroll
                for (int i = 0; i < 4; i++)
                    bf[np][i] = f2tf(__uint_as_float(bf[np][i]));
            #pragma unroll
            for (int mt = 0; mt < 2; mt++)
                #pragma unroll
                for (int nt = 0; nt < 8; nt++)
                    mma_tf32(acc[mt][nt], af[mt],
                             bf[nt >> 1][(nt & 1) * 2], bf[nt >> 1][(nt & 1) * 2 + 1]);
        }
        __syncthreads();
        if (kt + 3 < QNKT) load_stage(kt % QSTAGES, kt + 3);
        cp_commit();
    }

    const int n0g = n0 + wn * 64;
    const int h   = n0g >> 6;
    const int q2  = (lane & 3) * 2;
    #pragma unroll
    for (int mt = 0; mt < 2; mt++) {
        #pragma unroll
        for (int rh = 0; rh < 2; rh++) {
            int mrow = m0 + wm * 32 + mt * 16 + (lane >> 2) + rh * 8;
            int b = mrow >> 11;
            int s = mrow & (SEQ - 1);
            float* op = out + (((size_t)(b * NH + h) * SEQ + s) * HD);
            #pragma unroll
            for (int nt = 0; nt < 8; nt++) {
                int d = nt * 8 + q2;
                float2 bb = *(const float2*)&bias[n0g + d];
                float2 r = make_float2(acc[mt][nt][rh * 2 + 0] + bb.x,
                                       acc[mt][nt][rh * 2 + 1] + bb.y);
                *(float2*)&op[d] = r;
            }
        }
    }
}

// ============================================================================
// Flash attention v2: CTA = 128 queries of one (b,h), 4 warps x 32 q rows.
// 64-key tiles processed as two 32-key halves (halves S register footprint).
// P fragments built from S C-fragments via quad shuffles (no smem round-trip).
// Q tile persistent in smem; Q fragments re-materialized via ldmatrix.
// ============================================================================
#define APITCH 68
#define ATT_SMEM ((128 * APITCH + 64 * APITCH + 64 * APITCH + 64) * 4)

__global__ __launch_bounds__(128, 3) void attn_mma_kernel(
    const int* __restrict__ mask, float* __restrict__ out)
{
    extern __shared__ float sm[];
    float* Qs    = sm;                         // [128 q][68]
    float* Ks    = sm + 128 * APITCH;          // [64 kv][68]
    float* Vt    = Ks + 64 * APITCH;           // [64 d][68 kv]
    float* maskF = Vt + 64 * APITCH;

    const uint32_t sQ = smem_u32(Qs);
    const uint32_t sK = smem_u32(Ks);
    const uint32_t sV = smem_u32(Vt);

    const int tid  = threadIdx.x;
    const int lane = tid & 31;
    const int w    = tid >> 5;                 // warp -> q rows 32w..32w+31
    const int s0   = blockIdx.x * 128;
    const int bh   = blockIdx.y;
    const int b    = bh >> 4;

    const int a_row  = (lane & 15);
    const int a_kof  = (lane >> 4) * 4;
    const int b_row  = (lane & 7) + ((lane >> 4) << 3);
    const int b_kof  = ((lane >> 3) & 1) * 4;
    const int q2     = (lane & 3) * 2;
    const int r0     = lane >> 2;
    const int src_lo = (lane & 28) | ((lane >> 1) & 1);   // quad lane holding col j
    const int lodd   = lane & 1;

    // ---- load Q tile (tf32-converted), persistent ----
    const float* Qg = g_q + (size_t)(bh * SEQ + s0) * HD;
    #pragma unroll
    for (int it = 0; it < 16; it++) {
        int cid = tid + it * 128;
        int row = cid >> 4;
        int c   = (cid & 15) * 4;
        float4 v = *(const float4*)&Qg[row * HD + c];
        *(uint4*)&Qs[row * APITCH + c] =
            make_uint4(f2tf(v.x), f2tf(v.y), f2tf(v.z), f2tf(v.w));
    }

    float mI[2][2], l[2][2];
    float o[2][8][4];
    #pragma unroll
    for (int mt = 0; mt < 2; mt++) {
        mI[mt][0] = mI[mt][1] = -CUDART_INF_F;
        l[mt][0] = l[mt][1] = 0.f;
        #pragma unroll
        for (int dt = 0; dt < 8; dt++)
            o[mt][dt][0] = o[mt][dt][1] = o[mt][dt][2] = o[mt][dt][3] = 0.f;
    }

    const int vd  = tid & 63;
    const int vs0 = (tid >> 6) * 32;

    for (int kt = 0; kt < SEQ / 64; kt++) {
        __syncthreads();                       // prev iter consumers done
        const float* Kg = g_k + (size_t)(bh * SEQ + kt * 64) * HD;
        const float* Vg = g_v + (size_t)(bh * SEQ + kt * 64) * HD;
        #pragma unroll
        for (int it = 0; it < 8; it++) {
            int cid = tid + it * 128;
            int row = cid >> 4;
            int c   = (cid & 15) * 4;
            float4 v = *(const float4*)&Kg[row * HD + c];
            *(uint4*)&Ks[row * APITCH + c] =
                make_uint4(f2tf(v.x), f2tf(v.y), f2tf(v.z), f2tf(v.w));
        }
        #pragma unroll
        for (int g = 0; g < 8; g++) {
            int s = vs0 + g * 4;
            *(uint4*)&Vt[vd * APITCH + s] =
                make_uint4(f2tf(Vg[(s + 0) * HD + vd]),
                           f2tf(Vg[(s + 1) * HD + vd]),
                           f2tf(Vg[(s + 2) * HD + vd]),
                           f2tf(Vg[(s + 3) * HD + vd]));
        }
        if (tid < 64)
            maskF[tid] = mask[b * SEQ + kt * 64 + tid] ? 0.f : -CUDART_INF_F;
        __syncthreads();

        #pragma unroll
        for (int half = 0; half < 2; half++) {
            // ---- S = Q K^T over 32 keys ----
            float s[2][4][4];
            #pragma unroll
            for (int mt = 0; mt < 2; mt++)
                #pragma unroll
                for (int nt = 0; nt < 4; nt++)
                    s[mt][nt][0] = s[mt][nt][1] = s[mt][nt][2] = s[mt][nt][3] = 0.f;

            #pragma unroll
            for (int k8 = 0; k8 < 8; k8++) {
                uint32_t aq[2][4], bf[2][4];
                ldm4(aq[0], sQ + ((32 * w + a_row) * APITCH + k8 * 8 + a_kof) * 4);
                ldm4(aq[1], sQ + ((32 * w + 16 + a_row) * APITCH + k8 * 8 + a_kof) * 4);
                ldm4(bf[0], sK + ((half * 32 + b_row) * APITCH + k8 * 8 + b_kof) * 4);
                ldm4(bf[1], sK + ((half * 32 + 16 + b_row) * APITCH + k8 * 8 + b_kof) * 4);
                #pragma unroll
                for (int mt = 0; mt < 2; mt++)
                    #pragma unroll
                    for (int nt = 0; nt < 4; nt++)
                        mma_tf32(s[mt][nt], aq[mt],
                                 bf[nt >> 1][(nt & 1) * 2], bf[nt >> 1][(nt & 1) * 2 + 1]);
            }

            // ---- scale + mask + online softmax (per mt, 32 keys) ----
            #pragma unroll
            for (int mt = 0; mt < 2; mt++) {
                float mx0 = -CUDART_INF_F, mx1 = -CUDART_INF_F;
                #pragma unroll
                for (int nt = 0; nt < 4; nt++) {
                    float f0 = maskF[half * 32 + nt * 8 + q2];
                    float f1 = maskF[half * 32 + nt * 8 + q2 + 1];
                    s[mt][nt][0] = s[mt][nt][0] * 0.125f + f0;
                    s[mt][nt][1] = s[mt][nt][1] * 0.125f + f1;
                    s[mt][nt][2] = s[mt][nt][2] * 0.125f + f0;
                    s[mt][nt][3] = s[mt][nt][3] * 0.125f + f1;
                    mx0 = fmaxf(mx0, fmaxf(s[mt][nt][0], s[mt][nt][1]));
                    mx1 = fmaxf(mx1, fmaxf(s[mt][nt][2], s[mt][nt][3]));
                }
                mx0 = fmaxf(mx0, __shfl_xor_sync(0xffffffffu, mx0, 1));
                mx0 = fmaxf(mx0, __shfl_xor_sync(0xffffffffu, mx0, 2));
                mx1 = fmaxf(mx1, __shfl_xor_sync(0xffffffffu, mx1, 1));
                mx1 = fmaxf(mx1, __shfl_xor_sync(0xffffffffu, mx1, 2));

                float mn0 = fmaxf(mI[mt][0], mx0), mn1 = fmaxf(mI[mt][1], mx1);
                float mu0 = (mn0 == -CUDART_INF_F) ? 0.f : mn0;
                float mu1 = (mn1 == -CUDART_INF_F) ? 0.f : mn1;
                float al0 = __expf(mI[mt][0] - mu0), al1 = __expf(mI[mt][1] - mu1);
                float rs0 = 0.f, rs1 = 0.f;
                #pragma unroll
                for (int nt = 0; nt < 4; nt++) {
                    s[mt][nt][0] = __expf(s[mt][nt][0] - mu0);
                    s[mt][nt][1] = __expf(s[mt][nt][1] - mu0);
                    s[mt][nt][2] = __expf(s[mt][nt][2] - mu1);
                    s[mt][nt][3] = __expf(s[mt][nt][3] - mu1);
                    rs0 += s[mt][nt][0] + s[mt][nt][1];
                    rs1 += s[mt][nt][2] + s[mt][nt][3];
                }
                rs0 += __shfl_xor_sync(0xffffffffu, rs0, 1);
                rs0 += __shfl_xor_sync(0xffffffffu, rs0, 2);
                rs1 += __shfl_xor_sync(0xffffffffu, rs1, 1);
                rs1 += __shfl_xor_sync(0xffffffffu, rs1, 2);
                l[mt][0] = l[mt][0] * al0 + rs0; mI[mt][0] = mn0;
                l[mt][1] = l[mt][1] * al1 + rs1; mI[mt][1] = mn1;
                #pragma unroll
                for (int dt = 0; dt < 8; dt++) {
                    o[mt][dt][0] *= al0; o[mt][dt][1] *= al0;
                    o[mt][dt][2] *= al1; o[mt][dt][3] *= al1;
                }
            }

            // ---- O += P V  (P A-frags built via quad shuffles from S) ----
            #pragma unroll
            for (int k8p = 0; k8p < 4; k8p++) {
                uint32_t vf[4][4];
                #pragma unroll
                for (int np = 0; np < 4; np++)
                    ldm4(vf[np], sV + ((np * 16 + b_row) * APITCH
                                       + half * 32 + k8p * 8 + b_kof) * 4);
                #pragma unroll
                for (int mt = 0; mt < 2; mt++) {
                    float c0 = s[mt][k8p][0], c1 = s[mt][k8p][1];
                    float c2 = s[mt][k8p][2], c3 = s[mt][k8p][3];
                    float x0 = __shfl_sync(0xffffffffu, c0, src_lo);
                    float y0 = __shfl_sync(0xffffffffu, c1, src_lo);
                    float x1 = __shfl_sync(0xffffffffu, c2, src_lo);
                    float y1 = __shfl_sync(0xffffffffu, c3, src_lo);
                    float x2 = __shfl_sync(0xffffffffu, c0, src_lo + 2);
                    float y2 = __shfl_sync(0xffffffffu, c1, src_lo + 2);
                    float x3 = __shfl_sync(0xffffffffu, c2, src_lo + 2);
                    float y3 = __shfl_sync(0xffffffffu, c3, src_lo + 2);
                    uint32_t pa[4];
                    pa[0] = f2tf(lodd ? y0 : x0);
                    pa[1] = f2tf(lodd ? y1 : x1);
                    pa[2] = f2tf(lodd ? y2 : x2);
                    pa[3] = f2tf(lodd ? y3 : x3);
                    #pragma unroll
                    for (int dt = 0; dt < 8; dt++)
                        mma_tf32(o[mt][dt], pa,
                                 vf[dt >> 1][(dt & 1) * 2], vf[dt >> 1][(dt & 1) * 2 + 1]);
                }
            }
        }
    }

    // ---- epilogue ----
    const int h = bh & 15;
    #pragma unroll
    for (int mt = 0; mt < 2; mt++) {
        float inv0 = 1.0f / fmaxf(l[mt][0], 1e-30f);
        float inv1 = 1.0f / fmaxf(l[mt][1], 1e-30f);
        int row0 = s0 + 32 * w + mt * 16 + r0;
        float* op0 = out + (size_t)(b * SEQ + row0) * HID + h * HD;
        float* op1 = out + (size_t)(b * SEQ + row0 + 8) * HID + h * HD;
        #pragma unroll
        for (int dt = 0; dt < 8; dt++) {
            int d = dt * 8 + q2;
            *(float2*)&op0[d] = make_float2(o[mt][dt][0] * inv0, o[mt][dt][1] * inv0);
            *(float2*)&op1[d] = make_float2(o[mt][dt][2] * inv1, o[mt][dt][3] * inv1);
        }
    }
}

// ---------------------------------------------------------------------------
extern "C" void kernel_launch(void* const* d_in, const int* in_sizes, int n_in,
                              void* d_out, int out_size)
{
    const float* X    = (const float*)d_in[0];
    const int*   mask = (const int*)d_in[1];
    const float* Wq   = (const float*)d_in[2];
    const float* bq   = (const float*)d_in[3];
    const float* Wk   = (const float*)d_in[4];
    const float* bk   = (const float*)d_in[5];
    const float* Wv   = (const float*)d_in[6];
    const float* bv   = (const float*)d_in[7];
    float* out = (float*)d_out;

    cudaFuncSetAttribute(qkv_mma_kernel,
                         cudaFuncAttributeMaxDynamicSharedMemorySize, QKV_SMEM);
    qkv_mma_kernel<<<dim3(32, 8, 3), 256, QKV_SMEM>>>(X, Wq, bq, Wk, bk, Wv, bv);

    cudaFuncSetAttribute(attn_mma_kernel,
                         cudaFuncAttributeMaxDynamicSharedMemorySize, ATT_SMEM);
    attn_mma_kernel<<<dim3(SEQ / 128, BSZ * NH), 128, ATT_SMEM>>>(mask, out);
}

// round 6
// speedup vs baseline: 1.1379x; 1.1379x over previous
#include <cuda_runtime.h>
#include <math_constants.h>
#include <cstdint>

#define BSZ   2
#define SEQ   2048
#define HID   1024
#define NH    16
#define HD    64

// Scratch for projected Q/K/V, laid out [b*NH+h][s][d]
__device__ float g_q[BSZ * NH * SEQ * HD];
__device__ float g_k[BSZ * NH * SEQ * HD];
__device__ float g_v[BSZ * NH * SEQ * HD];

// ============================================================================
// helpers
// ============================================================================
__device__ __forceinline__ uint32_t smem_u32(const void* p) {
    uint32_t a;
    asm("{ .reg .u64 t; cvta.to.shared.u64 t, %1; cvt.u32.u64 %0, t; }"
        : "=r"(a) : "l"(p));
    return a;
}
__device__ __forceinline__ void cp16(uint32_t s, const void* g) {
    asm volatile("cp.async.cg.shared.global [%0], [%1], 16;" :: "r"(s), "l"(g));
}
__device__ __forceinline__ void cp_commit() {
    asm volatile("cp.async.commit_group;" ::: "memory");
}
__device__ __forceinline__ void cp_wait2() {
    asm volatile("cp.async.wait_group 2;" ::: "memory");
}
__device__ __forceinline__ void cp_wait0() {
    asm volatile("cp.async.wait_group 0;" ::: "memory");
}
__device__ __forceinline__ uint32_t f2tf(float f) {
    uint32_t r;
    asm("cvt.rna.tf32.f32 %0, %1;" : "=r"(r) : "f"(f));
    return r;
}
__device__ __forceinline__ void ldm4(uint32_t* r, uint32_t addr) {
    asm volatile("ldmatrix.sync.aligned.m8n8.x4.shared.b16 {%0,%1,%2,%3}, [%4];"
                 : "=r"(r[0]), "=r"(r[1]), "=r"(r[2]), "=r"(r[3]) : "r"(addr));
}
__device__ __forceinline__ void mma_tf32(float* c, const uint32_t* a,
                                         uint32_t b0, uint32_t b1) {
    asm volatile(
        "mma.sync.aligned.m16n8k8.row.col.f32.tf32.tf32.f32 "
        "{%0,%1,%2,%3}, {%4,%5,%6,%7}, {%8,%9}, {%0,%1,%2,%3};"
        : "+f"(c[0]), "+f"(c[1]), "+f"(c[2]), "+f"(c[3])
        : "r"(a[0]), "r"(a[1]), "r"(a[2]), "r"(a[3]), "r"(b0), "r"(b1));
}

// ============================================================================
// QKV projection (unchanged from R3): out[m][n] = sum_k X[m][k]*W[n][k] + b[n]
// ============================================================================
#define QPITCH   36
#define QA_BYTES (128 * QPITCH * 4)
#define QSTAGE   (2 * QA_BYTES)
#define QSTAGES  3
#define QKV_SMEM (QSTAGES * QSTAGE)
#define QNKT     (HID / 32)

__global__ __launch_bounds__(256) void qkv_mma_kernel(
    const float* __restrict__ X,
    const float* __restrict__ Wq, const float* __restrict__ bq,
    const float* __restrict__ Wk, const float* __restrict__ bk,
    const float* __restrict__ Wv, const float* __restrict__ bv)
{
    const float* W; const float* bias; float* out;
    if (blockIdx.z == 0)      { W = Wq; bias = bq; out = g_q; }
    else if (blockIdx.z == 1) { W = Wk; bias = bk; out = g_k; }
    else                      { W = Wv; bias = bv; out = g_v; }

    extern __shared__ char smem[];
    const uint32_t sb = smem_u32(smem);

    const int tid  = threadIdx.x;
    const int wid  = tid >> 5;
    const int lane = tid & 31;
    const int wm   = wid >> 1;
    const int wn   = wid & 1;
    const int m0   = blockIdx.x * 128;
    const int n0   = blockIdx.y * 128;

    const float* gA0 = X + (size_t)m0 * HID;
    const float* gB0 = W + (size_t)n0 * HID;

    auto load_stage = [&](int stage, int kt) {
        const uint32_t sA = sb + stage * QSTAGE;
        const uint32_t sB = sA + QA_BYTES;
        const float* gA = gA0 + kt * 32;
        const float* gB = gB0 + kt * 32;
        #pragma unroll
        for (int i = 0; i < 4; i++) {
            int cid = tid + (i << 8);
            int row = cid >> 3;
            int c   = cid & 7;
            uint32_t off = row * (QPITCH * 4) + c * 16;
            cp16(sA + off, gA + row * HID + c * 4);
            cp16(sB + off, gB + row * HID + c * 4);
        }
    };

    load_stage(0, 0); cp_commit();
    load_stage(1, 1); cp_commit();
    load_stage(2, 2); cp_commit();

    float acc[2][8][4];
    #pragma unroll
    for (int mt = 0; mt < 2; mt++)
        #pragma unroll
        for (int nt = 0; nt < 8; nt++)
            acc[mt][nt][0] = acc[mt][nt][1] = acc[mt][nt][2] = acc[mt][nt][3] = 0.f;

    const int a_row = (lane & 15);
    const int a_kof = (lane >> 4) * 4;
    const int b_row = (lane & 7) + ((lane >> 4) << 3);
    const int b_kof = ((lane >> 3) & 1) * 4;

    for (int kt = 0; kt < QNKT; kt++) {
        cp_wait2();
        __syncthreads();
        const uint32_t sA = sb + (kt % QSTAGES) * QSTAGE;
        const uint32_t sB = sA + QA_BYTES;

        #pragma unroll
        for (int k8 = 0; k8 < 4; k8++) {
            const int kc = k8 * 8;
            uint32_t af[2][4], bf[4][4];
            #pragma unroll
            for (int mt = 0; mt < 2; mt++)
                ldm4(af[mt], sA + ((wm * 32 + mt * 16 + a_row) * QPITCH + kc + a_kof) * 4);
            #pragma unroll
            for (int np = 0; np < 4; np++)
                ldm4(bf[np], sB + ((wn * 64 + np * 16 + b_row) * QPITCH + kc + b_kof) * 4);
            #pragma unroll
            for (int mt = 0; mt < 2; mt++)
                #pragma unroll
                for (int i = 0; i < 4; i++)
                    af[mt][i] = f2tf(__uint_as_float(af[mt][i]));
            #pragma unroll
            for (int np = 0; np < 4; np++)
                #pragma unroll
                for (int i = 0; i < 4; i++)
                    bf[np][i] = f2tf(__uint_as_float(bf[np][i]));
            #pragma unroll
            for (int mt = 0; mt < 2; mt++)
                #pragma unroll
                for (int nt = 0; nt < 8; nt++)
                    mma_tf32(acc[mt][nt], af[mt],
                             bf[nt >> 1][(nt & 1) * 2], bf[nt >> 1][(nt & 1) * 2 + 1]);
        }
        __syncthreads();
        if (kt + 3 < QNKT) load_stage(kt % QSTAGES, kt + 3);
        cp_commit();
    }

    const int n0g = n0 + wn * 64;
    const int h   = n0g >> 6;
    const int q2  = (lane & 3) * 2;
    #pragma unroll
    for (int mt = 0; mt < 2; mt++) {
        #pragma unroll
        for (int rh = 0; rh < 2; rh++) {
            int mrow = m0 + wm * 32 + mt * 16 + (lane >> 2) + rh * 8;
            int b = mrow >> 11;
            int s = mrow & (SEQ - 1);
            float* op = out + (((size_t)(b * NH + h) * SEQ + s) * HD);
            #pragma unroll
            for (int nt = 0; nt < 8; nt++) {
                int d = nt * 8 + q2;
                float2 bb = *(const float2*)&bias[n0g + d];
                float2 r = make_float2(acc[mt][nt][rh * 2 + 0] + bb.x,
                                       acc[mt][nt][rh * 2 + 1] + bb.y);
                *(float2*)&op[d] = r;
            }
        }
    }
}

// ============================================================================
// Flash attention v3 (fixed): 64 q/CTA, 4 warps x 16 q, grid 1024.
// K double-buffered via cp.async (raw fp32, cvt on fragments), V(kt+1) staged
// in registers across tile compute, mask double-buffered, P built via quad
// shuffles (no smem round-trip). Q persistent in smem.
// FIX vs R5: K tile loader covers the FULL 64x64 tile (1024 x 16B chunks,
// row = cid>>4, c = cid&15) in both prologue and steady state.
// ============================================================================
#define APITCH 68
#define ATILE  (64 * APITCH)
#define NKT    (SEQ / 64)
#define ATT_SMEM ((4 * ATILE) * 4 + 2 * 64 * 4)

__global__ __launch_bounds__(128, 3) void attn_mma_kernel(
    const int* __restrict__ mask, float* __restrict__ out)
{
    extern __shared__ float sm[];
    float* Qs   = sm;                          // [64 q][68] tf32
    float* Ksb  = sm + ATILE;                  // 2 x [64 kv][68] raw fp32
    float* Vt   = sm + 3 * ATILE;              // [64 d][68 kv] tf32
    int*   mskb = (int*)(sm + 4 * ATILE);      // 2 x [64]

    const uint32_t sQ  = smem_u32(Qs);
    const uint32_t sKb = smem_u32(Ksb);
    const uint32_t sV  = smem_u32(Vt);
    const uint32_t sM  = smem_u32(mskb);

    const int tid  = threadIdx.x;
    const int lane = tid & 31;
    const int w    = tid >> 5;
    const int s0   = blockIdx.x * 64;
    const int bh   = blockIdx.y;
    const int b    = bh >> 4;

    const int a_row  = (lane & 15);
    const int a_kof  = (lane >> 4) * 4;
    const int b_row  = (lane & 7) + ((lane >> 4) << 3);
    const int b_kof  = ((lane >> 3) & 1) * 4;
    const int q2     = (lane & 3) * 2;
    const int r0     = lane >> 2;
    const int src_lo = (lane & 28) | ((lane >> 1) & 1);
    const int lodd   = lane & 1;

    const int vd  = tid & 63;
    const int vs0 = (tid >> 6) * 32;

    // ---- prologue ----
    const float* Qg = g_q + (size_t)(bh * SEQ + s0) * HD;
    #pragma unroll
    for (int it = 0; it < 8; it++) {
        int cid = tid + it * 128;
        int row = cid >> 4;
        int c   = (cid & 15) * 4;
        float4 v = *(const float4*)&Qg[row * HD + c];
        *(uint4*)&Qs[row * APITCH + c] =
            make_uint4(f2tf(v.x), f2tf(v.y), f2tf(v.z), f2tf(v.w));
    }
    {
        const float* Kg = g_k + (size_t)bh * SEQ * HD;
        #pragma unroll
        for (int i = 0; i < 8; i++) {
            int cid = tid + (i << 7);          // 0..1023
            int row = cid >> 4;                // 0..63
            int c   = cid & 15;                // 16B chunk within 256B row
            cp16(sKb + row * (APITCH * 4) + c * 16, Kg + row * HD + c * 4);
        }
        if (tid < 16) cp16(sM + tid * 16, mask + b * SEQ + tid * 4);
        cp_commit();
        const float* Vg = g_v + (size_t)bh * SEQ * HD;
        #pragma unroll
        for (int g = 0; g < 8; g++) {
            int s = vs0 + g * 4;
            *(uint4*)&Vt[vd * APITCH + s] =
                make_uint4(f2tf(Vg[(s + 0) * HD + vd]),
                           f2tf(Vg[(s + 1) * HD + vd]),
                           f2tf(Vg[(s + 2) * HD + vd]),
                           f2tf(Vg[(s + 3) * HD + vd]));
        }
        cp_wait0();
    }
    __syncthreads();

    float mI0 = -CUDART_INF_F, mI1 = -CUDART_INF_F, l0 = 0.f, l1 = 0.f;
    float o[8][4];
    #pragma unroll
    for (int dt = 0; dt < 8; dt++)
        o[dt][0] = o[dt][1] = o[dt][2] = o[dt][3] = 0.f;

    for (int kt = 0; kt < NKT; kt++) {
        const int cur = kt & 1;
        const bool has_next = (kt + 1 < NKT);

        if (has_next) {
            const float* Kg = g_k + (size_t)(bh * SEQ + (kt + 1) * 64) * HD;
            const uint32_t sKn = sKb + (cur ^ 1) * (ATILE * 4);
            #pragma unroll
            for (int i = 0; i < 8; i++) {
                int cid = tid + (i << 7);      // 0..1023
                int row = cid >> 4;            // 0..63
                int c   = cid & 15;
                cp16(sKn + row * (APITCH * 4) + c * 16, Kg + row * HD + c * 4);
            }
            if (tid < 16)
                cp16(sM + (cur ^ 1) * 256 + tid * 16,
                     mask + b * SEQ + (kt + 1) * 64 + tid * 4);
            cp_commit();
        }

        float vreg[32];
        if (has_next) {
            const float* Vg = g_v + (size_t)(bh * SEQ + (kt + 1) * 64) * HD;
            #pragma unroll
            for (int g = 0; g < 8; g++) {
                int s = vs0 + g * 4;
                vreg[g * 4 + 0] = Vg[(s + 0) * HD + vd];
                vreg[g * 4 + 1] = Vg[(s + 1) * HD + vd];
                vreg[g * 4 + 2] = Vg[(s + 2) * HD + vd];
                vreg[g * 4 + 3] = Vg[(s + 3) * HD + vd];
            }
        }

        // ---- S = Q K^T ----
        const uint32_t sKc = sKb + cur * (ATILE * 4);
        float s[8][4];
        #pragma unroll
        for (int nt = 0; nt < 8; nt++)
            s[nt][0] = s[nt][1] = s[nt][2] = s[nt][3] = 0.f;
        #pragma unroll
        for (int k8 = 0; k8 < 8; k8++) {
            uint32_t aq[4], bf[4][4];
            ldm4(aq, sQ + ((16 * w + a_row) * APITCH + k8 * 8 + a_kof) * 4);
            #pragma unroll
            for (int np = 0; np < 4; np++) {
                ldm4(bf[np], sKc + ((np * 16 + b_row) * APITCH + k8 * 8 + b_kof) * 4);
                #pragma unroll
                for (int i = 0; i < 4; i++)
                    bf[np][i] = f2tf(__uint_as_float(bf[np][i]));
            }
            #pragma unroll
            for (int nt = 0; nt < 8; nt++)
                mma_tf32(s[nt], aq,
                         bf[nt >> 1][(nt & 1) * 2], bf[nt >> 1][(nt & 1) * 2 + 1]);
        }

        // ---- scale + mask + online softmax ----
        const int* mk = mskb + cur * 64;
        float mx0 = -CUDART_INF_F, mx1 = -CUDART_INF_F;
        #pragma unroll
        for (int nt = 0; nt < 8; nt++) {
            float f0 = mk[nt * 8 + q2]     ? 0.f : -CUDART_INF_F;
            float f1 = mk[nt * 8 + q2 + 1] ? 0.f : -CUDART_INF_F;
            s[nt][0] = s[nt][0] * 0.125f + f0;
            s[nt][1] = s[nt][1] * 0.125f + f1;
            s[nt][2] = s[nt][2] * 0.125f + f0;
            s[nt][3] = s[nt][3] * 0.125f + f1;
            mx0 = fmaxf(mx0, fmaxf(s[nt][0], s[nt][1]));
            mx1 = fmaxf(mx1, fmaxf(s[nt][2], s[nt][3]));
        }
        mx0 = fmaxf(mx0, __shfl_xor_sync(0xffffffffu, mx0, 1));
        mx0 = fmaxf(mx0, __shfl_xor_sync(0xffffffffu, mx0, 2));
        mx1 = fmaxf(mx1, __shfl_xor_sync(0xffffffffu, mx1, 1));
        mx1 = fmaxf(mx1, __shfl_xor_sync(0xffffffffu, mx1, 2));

        float mn0 = fmaxf(mI0, mx0), mn1 = fmaxf(mI1, mx1);
        float mu0 = (mn0 == -CUDART_INF_F) ? 0.f : mn0;
        float mu1 = (mn1 == -CUDART_INF_F) ? 0.f : mn1;
        float al0 = __expf(mI0 - mu0), al1 = __expf(mI1 - mu1);
        float rs0 = 0.f, rs1 = 0.f;
        #pragma unroll
        for (int nt = 0; nt < 8; nt++) {
            s[nt][0] = __expf(s[nt][0] - mu0);
            s[nt][1] = __expf(s[nt][1] - mu0);
            s[nt][2] = __expf(s[nt][2] - mu1);
            s[nt][3] = __expf(s[nt][3] - mu1);
            rs0 += s[nt][0] + s[nt][1];
            rs1 += s[nt][2] + s[nt][3];
        }
        rs0 += __shfl_xor_sync(0xffffffffu, rs0, 1);
        rs0 += __shfl_xor_sync(0xffffffffu, rs0, 2);
        rs1 += __shfl_xor_sync(0xffffffffu, rs1, 1);
        rs1 += __shfl_xor_sync(0xffffffffu, rs1, 2);
        l0 = l0 * al0 + rs0; mI0 = mn0;
        l1 = l1 * al1 + rs1; mI1 = mn1;
        #pragma unroll
        for (int dt = 0; dt < 8; dt++) {
            o[dt][0] *= al0; o[dt][1] *= al0;
            o[dt][2] *= al1; o[dt][3] *= al1;
        }

        // ---- O += P V (P A-frags via quad shuffles) ----
        #pragma unroll
        for (int k8p = 0; k8p < 8; k8p++) {
            uint32_t vf[4][4];
            #pragma unroll
            for (int np = 0; np < 4; np++)
                ldm4(vf[np], sV + ((np * 16 + b_row) * APITCH + k8p * 8 + b_kof) * 4);
            float c0 = s[k8p][0], c1 = s[k8p][1];
            float c2 = s[k8p][2], c3 = s[k8p][3];
            float x0 = __shfl_sync(0xffffffffu, c0, src_lo);
            float y0 = __shfl_sync(0xffffffffu, c1, src_lo);
            float x1 = __shfl_sync(0xffffffffu, c2, src_lo);
            float y1 = __shfl_sync(0xffffffffu, c3, src_lo);
            float x2 = __shfl_sync(0xffffffffu, c0, src_lo + 2);
            float y2 = __shfl_sync(0xffffffffu, c1, src_lo + 2);
            float x3 = __shfl_sync(0xffffffffu, c2, src_lo + 2);
            float y3 = __shfl_sync(0xffffffffu, c3, src_lo + 2);
            uint32_t pa[4];
            pa[0] = f2tf(lodd ? y0 : x0);
            pa[1] = f2tf(lodd ? y1 : x1);
            pa[2] = f2tf(lodd ? y2 : x2);
            pa[3] = f2tf(lodd ? y3 : x3);
            #pragma unroll
            for (int dt = 0; dt < 8; dt++)
                mma_tf32(o[dt], pa,
                         vf[dt >> 1][(dt & 1) * 2], vf[dt >> 1][(dt & 1) * 2 + 1]);
        }

        // ---- rotate V buffer ----
        __syncthreads();
        if (has_next) {
            #pragma unroll
            for (int g = 0; g < 8; g++) {
                int s = vs0 + g * 4;
                *(uint4*)&Vt[vd * APITCH + s] =
                    make_uint4(f2tf(vreg[g * 4 + 0]), f2tf(vreg[g * 4 + 1]),
                               f2tf(vreg[g * 4 + 2]), f2tf(vreg[g * 4 + 3]));
            }
        }
        cp_wait0();
        __syncthreads();
    }

    // ---- epilogue ----
    float inv0 = 1.0f / fmaxf(l0, 1e-30f);
    float inv1 = 1.0f / fmaxf(l1, 1e-30f);
    const int h = bh & 15;
    const int row0 = s0 + 16 * w + r0;
    float* op0 = out + (size_t)(b * SEQ + row0) * HID + h * HD;
    float* op1 = out + (size_t)(b * SEQ + row0 + 8) * HID + h * HD;
    #pragma unroll
    for (int dt = 0; dt < 8; dt++) {
        int d = dt * 8 + q2;
        *(float2*)&op0[d] = make_float2(o[dt][0] * inv0, o[dt][1] * inv0);
        *(float2*)&op1[d] = make_float2(o[dt][2] * inv1, o[dt][3] * inv1);
    }
}

// ---------------------------------------------------------------------------
extern "C" void kernel_launch(void* const* d_in, const int* in_sizes, int n_in,
                              void* d_out, int out_size)
{
    const float* X    = (const float*)d_in[0];
    const int*   mask = (const int*)d_in[1];
    const float* Wq   = (const float*)d_in[2];
    const float* bq   = (const float*)d_in[3];
    const float* Wk   = (const float*)d_in[4];
    const float* bk   = (const float*)d_in[5];
    const float* Wv   = (const float*)d_in[6];
    const float* bv   = (const float*)d_in[7];
    float* out = (float*)d_out;

    cudaFuncSetAttribute(qkv_mma_kernel,
                         cudaFuncAttributeMaxDynamicSharedMemorySize, QKV_SMEM);
    qkv_mma_kernel<<<dim3(32, 8, 3), 256, QKV_SMEM>>>(X, Wq, bq, Wk, bk, Wv, bv);

    cudaFuncSetAttribute(attn_mma_kernel,
                         cudaFuncAttributeMaxDynamicSharedMemorySize, ATT_SMEM);
    attn_mma_kernel<<<dim3(SEQ / 64, BSZ * NH), 128, ATT_SMEM>>>(mask, out);
}

// round 7
// speedup vs baseline: 1.2076x; 1.0612x over previous
#include <cuda_runtime.h>
#include <math_constants.h>
#include <cstdint>

#define BSZ   2
#define SEQ   2048
#define HID   1024
#define NH    16
#define HD    64

// Scratch: projected Q/K/V [b*NH+h][s][d] (tf32-rounded bits), plus
// tf32-preconverted inputs/weights.
__device__ float g_q[BSZ * NH * SEQ * HD];
__device__ float g_k[BSZ * NH * SEQ * HD];
__device__ float g_v[BSZ * NH * SEQ * HD];
__device__ float g_xt[BSZ * SEQ * HID];
__device__ float g_wt[3 * HID * HID];

// ============================================================================
// helpers
// ============================================================================
__device__ __forceinline__ uint32_t smem_u32(const void* p) {
    uint32_t a;
    asm("{ .reg .u64 t; cvta.to.shared.u64 t, %1; cvt.u32.u64 %0, t; }"
        : "=r"(a) : "l"(p));
    return a;
}
__device__ __forceinline__ void cp16(uint32_t s, const void* g) {
    asm volatile("cp.async.cg.shared.global [%0], [%1], 16;" :: "r"(s), "l"(g));
}
__device__ __forceinline__ void cp_commit() {
    asm volatile("cp.async.commit_group;" ::: "memory");
}
__device__ __forceinline__ void cp_wait2() {
    asm volatile("cp.async.wait_group 2;" ::: "memory");
}
__device__ __forceinline__ void cp_wait0() {
    asm volatile("cp.async.wait_group 0;" ::: "memory");
}
__device__ __forceinline__ uint32_t f2tf(float f) {
    uint32_t r;
    asm("cvt.rna.tf32.f32 %0, %1;" : "=r"(r) : "f"(f));
    return r;
}
__device__ __forceinline__ void ldm4(uint32_t* r, uint32_t addr) {
    asm volatile("ldmatrix.sync.aligned.m8n8.x4.shared.b16 {%0,%1,%2,%3}, [%4];"
                 : "=r"(r[0]), "=r"(r[1]), "=r"(r[2]), "=r"(r[3]) : "r"(addr));
}
__device__ __forceinline__ void mma_tf32(float* c, const uint32_t* a,
                                         uint32_t b0, uint32_t b1) {
    asm volatile(
        "mma.sync.aligned.m16n8k8.row.col.f32.tf32.tf32.f32 "
        "{%0,%1,%2,%3}, {%4,%5,%6,%7}, {%8,%9}, {%0,%1,%2,%3};"
        : "+f"(c[0]), "+f"(c[1]), "+f"(c[2]), "+f"(c[3])
        : "r"(a[0]), "r"(a[1]), "r"(a[2]), "r"(a[3]), "r"(b0), "r"(b1));
}

// ============================================================================
// Pre-pass: tf32-round X and the three weight matrices.
// ============================================================================
__global__ __launch_bounds__(256) void cvt_kernel(
    const float* __restrict__ X,
    const float* __restrict__ Wq,
    const float* __restrict__ Wk,
    const float* __restrict__ Wv)
{
    const int tid    = blockIdx.x * blockDim.x + threadIdx.x;
    const int stride = gridDim.x * blockDim.x;
    const int NX = BSZ * SEQ * HID / 4;
    for (int i = tid; i < NX; i += stride) {
        float4 v = ((const float4*)X)[i];
        ((uint4*)g_xt)[i] = make_uint4(f2tf(v.x), f2tf(v.y), f2tf(v.z), f2tf(v.w));
    }
    const int NW = HID * HID / 4;
    uint4* wq = (uint4*)g_wt;
    uint4* wk = (uint4*)(g_wt + HID * HID);
    uint4* wv = (uint4*)(g_wt + 2 * HID * HID);
    for (int i = tid; i < NW; i += stride) {
        float4 a = ((const float4*)Wq)[i];
        wq[i] = make_uint4(f2tf(a.x), f2tf(a.y), f2tf(a.z), f2tf(a.w));
        float4 b = ((const float4*)Wk)[i];
        wk[i] = make_uint4(f2tf(b.x), f2tf(b.y), f2tf(b.z), f2tf(b.w));
        float4 c = ((const float4*)Wv)[i];
        wv[i] = make_uint4(f2tf(c.x), f2tf(c.y), f2tf(c.z), f2tf(c.w));
    }
}

// ============================================================================
// QKV projection: operands pre-rounded to tf32 -> no cvt in mainloop.
// Epilogue rounds (acc + bias) to tf32 so attention needs no cvt either.
// ============================================================================
#define QPITCH   36
#define QA_BYTES (128 * QPITCH * 4)
#define QSTAGE   (2 * QA_BYTES)
#define QSTAGES  3
#define QKV_SMEM (QSTAGES * QSTAGE)
#define QNKT     (HID / 32)

__global__ __launch_bounds__(256) void qkv_mma_kernel(
    const float* __restrict__ bq,
    const float* __restrict__ bk,
    const float* __restrict__ bv)
{
    const float* bias; float* out;
    if (blockIdx.z == 0)      { bias = bq; out = g_q; }
    else if (blockIdx.z == 1) { bias = bk; out = g_k; }
    else                      { bias = bv; out = g_v; }
    const float* W = g_wt + (size_t)blockIdx.z * HID * HID;

    extern __shared__ char smem[];
    const uint32_t sb = smem_u32(smem);

    const int tid  = threadIdx.x;
    const int wid  = tid >> 5;
    const int lane = tid & 31;
    const int wm   = wid >> 1;
    const int wn   = wid & 1;
    const int m0   = blockIdx.x * 128;
    const int n0   = blockIdx.y * 128;

    const float* gA0 = g_xt + (size_t)m0 * HID;
    const float* gB0 = W + (size_t)n0 * HID;

    auto load_stage = [&](int stage, int kt) {
        const uint32_t sA = sb + stage * QSTAGE;
        const uint32_t sB = sA + QA_BYTES;
        const float* gA = gA0 + kt * 32;
        const float* gB = gB0 + kt * 32;
        #pragma unroll
        for (int i = 0; i < 4; i++) {
            int cid = tid + (i << 8);
            int row = cid >> 3;
            int c   = cid & 7;
            uint32_t off = row * (QPITCH * 4) + c * 16;
            cp16(sA + off, gA + row * HID + c * 4);
            cp16(sB + off, gB + row * HID + c * 4);
        }
    };

    load_stage(0, 0); cp_commit();
    load_stage(1, 1); cp_commit();
    load_stage(2, 2); cp_commit();

    float acc[2][8][4];
    #pragma unroll
    for (int mt = 0; mt < 2; mt++)
        #pragma unroll
        for (int nt = 0; nt < 8; nt++)
            acc[mt][nt][0] = acc[mt][nt][1] = acc[mt][nt][2] = acc[mt][nt][3] = 0.f;

    const int a_row = (lane & 15);
    const int a_kof = (lane >> 4) * 4;
    const int b_row = (lane & 7) + ((lane >> 4) << 3);
    const int b_kof = ((lane >> 3) & 1) * 4;

    for (int kt = 0; kt < QNKT; kt++) {
        cp_wait2();
        __syncthreads();
        const uint32_t sA = sb + (kt % QSTAGES) * QSTAGE;
        const uint32_t sB = sA + QA_BYTES;

        #pragma unroll
        for (int k8 = 0; k8 < 4; k8++) {
            const int kc = k8 * 8;
            uint32_t af[2][4], bf[4][4];
            #pragma unroll
            for (int mt = 0; mt < 2; mt++)
                ldm4(af[mt], sA + ((wm * 32 + mt * 16 + a_row) * QPITCH + kc + a_kof) * 4);
            #pragma unroll
            for (int np = 0; np < 4; np++)
                ldm4(bf[np], sB + ((wn * 64 + np * 16 + b_row) * QPITCH + kc + b_kof) * 4);
            #pragma unroll
            for (int mt = 0; mt < 2; mt++)
                #pragma unroll
                for (int nt = 0; nt < 8; nt++)
                    mma_tf32(acc[mt][nt], af[mt],
                             bf[nt >> 1][(nt & 1) * 2], bf[nt >> 1][(nt & 1) * 2 + 1]);
        }
        __syncthreads();
        if (kt + 3 < QNKT) load_stage(kt % QSTAGES, kt + 3);
        cp_commit();
    }

    const int n0g = n0 + wn * 64;
    const int h   = n0g >> 6;
    const int q2  = (lane & 3) * 2;
    #pragma unroll
    for (int mt = 0; mt < 2; mt++) {
        #pragma unroll
        for (int rh = 0; rh < 2; rh++) {
            int mrow = m0 + wm * 32 + mt * 16 + (lane >> 2) + rh * 8;
            int b = mrow >> 11;
            int s = mrow & (SEQ - 1);
            float* op = out + (((size_t)(b * NH + h) * SEQ + s) * HD);
            #pragma unroll
            for (int nt = 0; nt < 8; nt++) {
                int d = nt * 8 + q2;
                float2 bb = *(const float2*)&bias[n0g + d];
                uint2 r = make_uint2(f2tf(acc[mt][nt][rh * 2 + 0] + bb.x),
                                     f2tf(acc[mt][nt][rh * 2 + 1] + bb.y));
                *(uint2*)&op[d] = r;
            }
        }
    }
}

// ============================================================================
// Flash attention v4: as R6, but Q/K/V arrive pre-rounded to tf32 ->
// zero cvt on Q/K/V paths; Q loaded via cp.async; only P cvts remain.
// ============================================================================
#define APITCH 68
#define ATILE  (64 * APITCH)
#define NKT    (SEQ / 64)
#define ATT_SMEM ((4 * ATILE) * 4 + 2 * 64 * 4)

__global__ __launch_bounds__(128, 3) void attn_mma_kernel(
    const int* __restrict__ mask, float* __restrict__ out)
{
    extern __shared__ float sm[];
    float* Qs   = sm;                          // [64 q][68] tf32
    float* Ksb  = sm + ATILE;                  // 2 x [64 kv][68] tf32
    float* Vt   = sm + 3 * ATILE;              // [64 d][68 kv] tf32
    int*   mskb = (int*)(sm + 4 * ATILE);      // 2 x [64]

    const uint32_t sQ  = smem_u32(Qs);
    const uint32_t sKb = smem_u32(Ksb);
    const uint32_t sV  = smem_u32(Vt);
    const uint32_t sM  = smem_u32(mskb);

    const int tid  = threadIdx.x;
    const int lane = tid & 31;
    const int w    = tid >> 5;
    const int s0   = blockIdx.x * 64;
    const int bh   = blockIdx.y;
    const int b    = bh >> 4;

    const int a_row  = (lane & 15);
    const int a_kof  = (lane >> 4) * 4;
    const int b_row  = (lane & 7) + ((lane >> 4) << 3);
    const int b_kof  = ((lane >> 3) & 1) * 4;
    const int q2     = (lane & 3) * 2;
    const int r0     = lane >> 2;
    const int src_lo = (lane & 28) | ((lane >> 1) & 1);
    const int lodd   = lane & 1;

    const int vd  = tid & 63;
    const int vs0 = (tid >> 6) * 32;

    // ---- prologue: Q + K(0) + mask(0) via cp.async, V(0) direct ----
    {
        const float* Qg = g_q + (size_t)(bh * SEQ + s0) * HD;
        const float* Kg = g_k + (size_t)bh * SEQ * HD;
        #pragma unroll
        for (int i = 0; i < 8; i++) {
            int cid = tid + (i << 7);          // 0..1023
            int row = cid >> 4;                // 0..63
            int c   = cid & 15;                // 16B chunk
            cp16(sQ  + row * (APITCH * 4) + c * 16, Qg + row * HD + c * 4);
            cp16(sKb + row * (APITCH * 4) + c * 16, Kg + row * HD + c * 4);
        }
        if (tid < 16) cp16(sM + tid * 16, mask + b * SEQ + tid * 4);
        cp_commit();
        const float* Vg = g_v + (size_t)bh * SEQ * HD;
        #pragma unroll
        for (int g = 0; g < 8; g++) {
            int s = vs0 + g * 4;
            *(float4*)&Vt[vd * APITCH + s] =
                make_float4(Vg[(s + 0) * HD + vd], Vg[(s + 1) * HD + vd],
                            Vg[(s + 2) * HD + vd], Vg[(s + 3) * HD + vd]);
        }
        cp_wait0();
    }
    __syncthreads();

    float mI0 = -CUDART_INF_F, mI1 = -CUDART_INF_F, l0 = 0.f, l1 = 0.f;
    float o[8][4];
    #pragma unroll
    for (int dt = 0; dt < 8; dt++)
        o[dt][0] = o[dt][1] = o[dt][2] = o[dt][3] = 0.f;

    for (int kt = 0; kt < NKT; kt++) {
        const int cur = kt & 1;
        const bool has_next = (kt + 1 < NKT);

        if (has_next) {
            const float* Kg = g_k + (size_t)(bh * SEQ + (kt + 1) * 64) * HD;
            const uint32_t sKn = sKb + (cur ^ 1) * (ATILE * 4);
            #pragma unroll
            for (int i = 0; i < 8; i++) {
                int cid = tid + (i << 7);
                int row = cid >> 4;
                int c   = cid & 15;
                cp16(sKn + row * (APITCH * 4) + c * 16, Kg + row * HD + c * 4);
            }
            if (tid < 16)
                cp16(sM + (cur ^ 1) * 256 + tid * 16,
                     mask + b * SEQ + (kt + 1) * 64 + tid * 4);
            cp_commit();
        }

        float vreg[32];
        if (has_next) {
            const float* Vg = g_v + (size_t)(bh * SEQ + (kt + 1) * 64) * HD;
            #pragma unroll
            for (int g = 0; g < 8; g++) {
                int s = vs0 + g * 4;
                vreg[g * 4 + 0] = Vg[(s + 0) * HD + vd];
                vreg[g * 4 + 1] = Vg[(s + 1) * HD + vd];
                vreg[g * 4 + 2] = Vg[(s + 2) * HD + vd];
                vreg[g * 4 + 3] = Vg[(s + 3) * HD + vd];
            }
        }

        // ---- S = Q K^T (no cvt: operands pre-rounded) ----
        const uint32_t sKc = sKb + cur * (ATILE * 4);
        float s[8][4];
        #pragma unroll
        for (int nt = 0; nt < 8; nt++)
            s[nt][0] = s[nt][1] = s[nt][2] = s[nt][3] = 0.f;
        #pragma unroll
        for (int k8 = 0; k8 < 8; k8++) {
            uint32_t aq[4], bf[4][4];
            ldm4(aq, sQ + ((16 * w + a_row) * APITCH + k8 * 8 + a_kof) * 4);
            #pragma unroll
            for (int np = 0; np < 4; np++)
                ldm4(bf[np], sKc + ((np * 16 + b_row) * APITCH + k8 * 8 + b_kof) * 4);
            #pragma unroll
            for (int nt = 0; nt < 8; nt++)
                mma_tf32(s[nt], aq,
                         bf[nt >> 1][(nt & 1) * 2], bf[nt >> 1][(nt & 1) * 2 + 1]);
        }

        // ---- scale + mask + online softmax ----
        const int* mk = mskb + cur * 64;
        float mx0 = -CUDART_INF_F, mx1 = -CUDART_INF_F;
        #pragma unroll
        for (int nt = 0; nt < 8; nt++) {
            float f0 = mk[nt * 8 + q2]     ? 0.f : -CUDART_INF_F;
            float f1 = mk[nt * 8 + q2 + 1] ? 0.f : -CUDART_INF_F;
            s[nt][0] = s[nt][0] * 0.125f + f0;
            s[nt][1] = s[nt][1] * 0.125f + f1;
            s[nt][2] = s[nt][2] * 0.125f + f0;
            s[nt][3] = s[nt][3] * 0.125f + f1;
            mx0 = fmaxf(mx0, fmaxf(s[nt][0], s[nt][1]));
            mx1 = fmaxf(mx1, fmaxf(s[nt][2], s[nt][3]));
        }
        mx0 = fmaxf(mx0, __shfl_xor_sync(0xffffffffu, mx0, 1));
        mx0 = fmaxf(mx0, __shfl_xor_sync(0xffffffffu, mx0, 2));
        mx1 = fmaxf(mx1, __shfl_xor_sync(0xffffffffu, mx1, 1));
        mx1 = fmaxf(mx1, __shfl_xor_sync(0xffffffffu, mx1, 2));

        float mn0 = fmaxf(mI0, mx0), mn1 = fmaxf(mI1, mx1);
        float mu0 = (mn0 == -CUDART_INF_F) ? 0.f : mn0;
        float mu1 = (mn1 == -CUDART_INF_F) ? 0.f : mn1;
        float al0 = __expf(mI0 - mu0), al1 = __expf(mI1 - mu1);
        float rs0 = 0.f, rs1 = 0.f;
        #pragma unroll
        for (int nt = 0; nt < 8; nt++) {
            s[nt][0] = __expf(s[nt][0] - mu0);
            s[nt][1] = __expf(s[nt][1] - mu0);
            s[nt][2] = __expf(s[nt][2] - mu1);
            s[nt][3] = __expf(s[nt][3] - mu1);
            rs0 += s[nt][0] + s[nt][1];
            rs1 += s[nt][2] + s[nt][3];
        }
        rs0 += __shfl_xor_sync(0xffffffffu, rs0, 1);
        rs0 += __shfl_xor_sync(0xffffffffu, rs0, 2);
        rs1 += __shfl_xor_sync(0xffffffffu, rs1, 1);
        rs1 += __shfl_xor_sync(0xffffffffu, rs1, 2);
        l0 = l0 * al0 + rs0; mI0 = mn0;
        l1 = l1 * al1 + rs1; mI1 = mn1;
        #pragma unroll
        for (int dt = 0; dt < 8; dt++) {
            o[dt][0] *= al0; o[dt][1] *= al0;
            o[dt][2] *= al1; o[dt][3] *= al1;
        }

        // ---- O += P V (P A-frags via quad shuffles; cvt only here) ----
        #pragma unroll
        for (int k8p = 0; k8p < 8; k8p++) {
            uint32_t vf[4][4];
            #pragma unroll
            for (int np = 0; np < 4; np++)
                ldm4(vf[np], sV + ((np * 16 + b_row) * APITCH + k8p * 8 + b_kof) * 4);
            float c0 = s[k8p][0], c1 = s[k8p][1];
            float c2 = s[k8p][2], c3 = s[k8p][3];
            float x0 = __shfl_sync(0xffffffffu, c0, src_lo);
            float y0 = __shfl_sync(0xffffffffu, c1, src_lo);
            float x1 = __shfl_sync(0xffffffffu, c2, src_lo);
            float y1 = __shfl_sync(0xffffffffu, c3, src_lo);
            float x2 = __shfl_sync(0xffffffffu, c0, src_lo + 2);
            float y2 = __shfl_sync(0xffffffffu, c1, src_lo + 2);
            float x3 = __shfl_sync(0xffffffffu, c2, src_lo + 2);
            float y3 = __shfl_sync(0xffffffffu, c3, src_lo + 2);
            uint32_t pa[4];
            pa[0] = f2tf(lodd ? y0 : x0);
            pa[1] = f2tf(lodd ? y1 : x1);
            pa[2] = f2tf(lodd ? y2 : x2);
            pa[3] = f2tf(lodd ? y3 : x3);
            #pragma unroll
            for (int dt = 0; dt < 8; dt++)
                mma_tf32(o[dt], pa,
                         vf[dt >> 1][(dt & 1) * 2], vf[dt >> 1][(dt & 1) * 2 + 1]);
        }

        // ---- rotate V buffer ----
        __syncthreads();
        if (has_next) {
            #pragma unroll
            for (int g = 0; g < 8; g++) {
                int s = vs0 + g * 4;
                *(float4*)&Vt[vd * APITCH + s] =
                    make_float4(vreg[g * 4 + 0], vreg[g * 4 + 1],
                                vreg[g * 4 + 2], vreg[g * 4 + 3]);
            }
        }
        cp_wait0();
        __syncthreads();
    }

    // ---- epilogue ----
    float inv0 = 1.0f / fmaxf(l0, 1e-30f);
    float inv1 = 1.0f / fmaxf(l1, 1e-30f);
    const int h = bh & 15;
    const int row0 = s0 + 16 * w + r0;
    float* op0 = out + (size_t)(b * SEQ + row0) * HID + h * HD;
    float* op1 = out + (size_t)(b * SEQ + row0 + 8) * HID + h * HD;
    #pragma unroll
    for (int dt = 0; dt < 8; dt++) {
        int d = dt * 8 + q2;
        *(float2*)&op0[d] = make_float2(o[dt][0] * inv0, o[dt][1] * inv0);
        *(float2*)&op1[d] = make_float2(o[dt][2] * inv1, o[dt][3] * inv1);
    }
}

// ---------------------------------------------------------------------------
extern "C" void kernel_launch(void* const* d_in, const int* in_sizes, int n_in,
                              void* d_out, int out_size)
{
    const float* X    = (const float*)d_in[0];
    const int*   mask = (const int*)d_in[1];
    const float* Wq   = (const float*)d_in[2];
    const float* bq   = (const float*)d_in[3];
    const float* Wk   = (const float*)d_in[4];
    const float* bk   = (const float*)d_in[5];
    const float* Wv   = (const float*)d_in[6];
    const float* bv   = (const float*)d_in[7];
    float* out = (float*)d_out;

    cvt_kernel<<<592, 256>>>(X, Wq, Wk, Wv);

    cudaFuncSetAttribute(qkv_mma_kernel,
                         cudaFuncAttributeMaxDynamicSharedMemorySize, QKV_SMEM);
    qkv_mma_kernel<<<dim3(32, 8, 3), 256, QKV_SMEM>>>(bq, bk, bv);

    cudaFuncSetAttribute(attn_mma_kernel,
                         cudaFuncAttributeMaxDynamicSharedMemorySize, ATT_SMEM);
    attn_mma_kernel<<<dim3(SEQ / 64, BSZ * NH), 128, ATT_SMEM>>>(mask, out);
}